// round 1
// baseline (speedup 1.0000x reference)
#include <cuda_runtime.h>
#include <cstdint>

#define NNODES 20000
#define NEDGES 320000
#define CH 256
#define ECH 64

// Scratch (allocation-free rule: __device__ globals)
__device__ float g_agg[NNODES * CH];
__device__ float g_h[NNODES * CH];
__device__ float g_sum[CH];
__device__ float g_sumsq[CH];
__device__ float g_scale[CH];
__device__ float g_shift[CH];

typedef unsigned long long ull;

__device__ __forceinline__ ull f2fma(ull a, ull b, ull c) {
    ull d;
    asm("fma.rn.f32x2 %0, %1, %2, %3;" : "=l"(d) : "l"(a), "l"(b), "l"(c));
    return d;
}
__device__ __forceinline__ ull f2add(ull a, ull b) {
    ull d;
    asm("add.rn.f32x2 %0, %1, %2;" : "=l"(d) : "l"(a), "l"(b));
    return d;
}
__device__ __forceinline__ ull pack2(float v) {
    unsigned r = __float_as_uint(v);
    ull d;
    asm("mov.b64 %0, {%1, %2};" : "=l"(d) : "r"(r), "r"(r));
    return d;
}
__device__ __forceinline__ float2 unpack2(ull v) {
    unsigned lo, hi;
    asm("mov.b64 {%0, %1}, %2;" : "=r"(lo), "=r"(hi) : "l"(v));
    return make_float2(__uint_as_float(lo), __uint_as_float(hi));
}

// ---------------------------------------------------------------------------
// K0: zero agg + stat accumulators
// ---------------------------------------------------------------------------
__global__ void zero_kernel() {
    int idx = blockIdx.x * blockDim.x + threadIdx.x;
    int stride = gridDim.x * blockDim.x;
    const int total = NNODES * CH / 4;
    float4* p = (float4*)g_agg;
    float4 z = make_float4(0.f, 0.f, 0.f, 0.f);
    for (int i = idx; i < total; i += stride) p[i] = z;
    if (idx < CH) { g_sum[idx] = 0.f; g_sumsq[idx] = 0.f; }
}

// ---------------------------------------------------------------------------
// K1: fused edge projection + message + scatter-add
//   e = edge_attr[e,:] @ W_edge      (64 x 256)
//   agg[dst] += x[src] * e
// 128 threads, thread t owns channels (2t, 2t+1) as one f32x2 lane.
// W_edge column-pair lives in 64 b64 registers, loaded once per block.
// ---------------------------------------------------------------------------
__global__ void __launch_bounds__(128) edge_kernel(
    const float* __restrict__ x, const int* __restrict__ ei,
    const float* __restrict__ ea, const float* __restrict__ W_edge, int E)
{
    const int t = threadIdx.x;  // 0..127 -> channel pair
    ull w[64];
    const ull* W2 = (const ull*)W_edge;  // [64][128] of float2
#pragma unroll
    for (int k = 0; k < 64; k++) w[k] = __ldg(&W2[k * 128 + t]);

    const int* src_p = ei;
    const int* dst_p = ei + E;

    for (int e = blockIdx.x; e < E; e += gridDim.x) {
        const float4* ea4 = (const float4*)(ea + (size_t)e * ECH);
        ull a0 = 0, a1 = 0, a2 = 0, a3 = 0;  // 4 independent acc chains
#pragma unroll
        for (int j = 0; j < 16; j++) {
            float4 q = __ldg(&ea4[j]);   // broadcast across warp
            a0 = f2fma(pack2(q.x), w[4 * j + 0], a0);
            a1 = f2fma(pack2(q.y), w[4 * j + 1], a1);
            a2 = f2fma(pack2(q.z), w[4 * j + 2], a2);
            a3 = f2fma(pack2(q.w), w[4 * j + 3], a3);
        }
        float2 s = unpack2(f2add(f2add(a0, a1), f2add(a2, a3)));
        int srcn = __ldg(&src_p[e]);
        int dstn = __ldg(&dst_p[e]);
        float2 xv = __ldg(((const float2*)(x + (size_t)srcn * CH)) + t);
        float mx = s.x * xv.x;
        float my = s.y * xv.y;
        float* ap = g_agg + (size_t)dstn * CH + 2 * t;
        atomicAdd(ap, mx);
        atomicAdd(ap + 1, my);
    }
}

// ---------------------------------------------------------------------------
// K2: node GEMMs. Virtual output [N, 512]:
//   cols   0..255 (yb 0..3):  h = relu(agg@W_rel + b_rel + x@W_root) -> g_h
//                             plus per-channel sum/sumsq for BN stats
//   cols 256..511 (yb 4..7):  res = x@W_res -> d_out
// BM=64, BN=64, BK=16, 128 threads, 8x4 thread tile as f32x2 pairs.
// ---------------------------------------------------------------------------
#define BM 64
#define BN 64
#define BK 16

__global__ void __launch_bounds__(128) node_gemm(
    const float* __restrict__ x,
    const float* __restrict__ W_rel, const float* __restrict__ b_rel,
    const float* __restrict__ W_root, const float* __restrict__ W_res,
    float* __restrict__ out)
{
    __shared__ float As[BK][BM + 4];  // pitch 68 floats = 272B (16B aligned)
    __shared__ float Bs[BK][BN];

    const int tid = threadIdx.x;
    const int tn = tid & 15;   // n group: cols tn*4 .. +3
    const int tm = tid >> 4;   // m group: rows tm*4..+3 and tm*4+32..+35
    const int mblk = blockIdx.x * BM;
    const int yb = blockIdx.y;
    const bool isH = (yb < 4);
    const int ncol0 = (isH ? yb : yb - 4) * BN;

    ull acc[8][2];
#pragma unroll
    for (int i = 0; i < 8; i++) { acc[i][0] = 0; acc[i][1] = 0; }

    const int nph = isH ? 2 : 1;
    for (int p = 0; p < nph; p++) {
        const float* A = (isH && p == 0) ? g_agg : x;
        const float* B = isH ? (p == 0 ? W_rel : W_root) : W_res;
        for (int k0 = 0; k0 < CH; k0 += BK) {
            // A tile, stored transposed As[k][m]
#pragma unroll
            for (int i = 0; i < 2; i++) {
                int idx = tid * 2 + i;      // 0..255
                int m = idx >> 2;           // 0..63
                int kq = (idx & 3) * 4;
                int row = mblk + m;
                float4 f = make_float4(0.f, 0.f, 0.f, 0.f);
                if (row < NNODES)
                    f = __ldg((const float4*)(A + (size_t)row * CH + k0 + kq));
                As[kq + 0][m] = f.x; As[kq + 1][m] = f.y;
                As[kq + 2][m] = f.z; As[kq + 3][m] = f.w;
            }
            // B tile
#pragma unroll
            for (int i = 0; i < 2; i++) {
                int idx = tid * 2 + i;
                int k = idx >> 4;           // 0..15
                int nq = (idx & 15) * 4;
                float4 f = __ldg((const float4*)(B + (size_t)(k0 + k) * CH + ncol0 + nq));
                *(float4*)&Bs[k][nq] = f;
            }
            __syncthreads();
#pragma unroll
            for (int k = 0; k < BK; k++) {
                float4 alo = *(const float4*)&As[k][tm * 4];
                float4 ahi = *(const float4*)&As[k][tm * 4 + 32];
                ulonglong2 bb = *(const ulonglong2*)&Bs[k][tn * 4];
                ull pa[8] = {pack2(alo.x), pack2(alo.y), pack2(alo.z), pack2(alo.w),
                             pack2(ahi.x), pack2(ahi.y), pack2(ahi.z), pack2(ahi.w)};
#pragma unroll
                for (int i = 0; i < 8; i++) {
                    acc[i][0] = f2fma(pa[i], bb.x, acc[i][0]);
                    acc[i][1] = f2fma(pa[i], bb.y, acc[i][1]);
                }
            }
            __syncthreads();
        }
    }

    const int c0 = ncol0 + tn * 4;
    if (isH) {
        float4 br = __ldg((const float4*)(b_rel + c0));
        float csum[4] = {0.f, 0.f, 0.f, 0.f};
        float csq[4] = {0.f, 0.f, 0.f, 0.f};
#pragma unroll
        for (int i = 0; i < 8; i++) {
            int row = mblk + tm * 4 + (i < 4 ? i : 32 + (i - 4));
            float2 v01 = unpack2(acc[i][0]);
            float2 v23 = unpack2(acc[i][1]);
            float v0 = fmaxf(v01.x + br.x, 0.f);
            float v1 = fmaxf(v01.y + br.y, 0.f);
            float v2 = fmaxf(v23.x + br.z, 0.f);
            float v3 = fmaxf(v23.y + br.w, 0.f);
            if (row < NNODES) {
                *(float4*)(g_h + (size_t)row * CH + c0) = make_float4(v0, v1, v2, v3);
                csum[0] += v0; csum[1] += v1; csum[2] += v2; csum[3] += v3;
                csq[0] += v0 * v0; csq[1] += v1 * v1;
                csq[2] += v2 * v2; csq[3] += v3 * v3;
            }
        }
#pragma unroll
        for (int j = 0; j < 4; j++) {
            atomicAdd(&g_sum[c0 + j], csum[j]);
            atomicAdd(&g_sumsq[c0 + j], csq[j]);
        }
    } else {
#pragma unroll
        for (int i = 0; i < 8; i++) {
            int row = mblk + tm * 4 + (i < 4 ? i : 32 + (i - 4));
            if (row < NNODES) {
                float2 v01 = unpack2(acc[i][0]);
                float2 v23 = unpack2(acc[i][1]);
                *(float4*)(out + (size_t)row * CH + c0) =
                    make_float4(v01.x, v01.y, v23.x, v23.y);
            }
        }
    }
}

// ---------------------------------------------------------------------------
// K3: fold BN stats into per-channel scale/shift
// ---------------------------------------------------------------------------
__global__ void bn_stats(const float* __restrict__ gamma, const float* __restrict__ beta) {
    int t = threadIdx.x;
    if (t < CH) {
        float m = g_sum[t] * (1.0f / NNODES);
        float var = g_sumsq[t] * (1.0f / NNODES) - m * m;
        float is = rsqrtf(var + 1e-5f);
        float sc = is * __ldg(&gamma[t]);
        g_scale[t] = sc;
        g_shift[t] = __ldg(&beta[t]) - m * sc;
    }
}

// ---------------------------------------------------------------------------
// K4: out = h * scale + shift + res   (res already in out)
// ---------------------------------------------------------------------------
__global__ void finalize(float* __restrict__ out) {
    int idx = blockIdx.x * blockDim.x + threadIdx.x;
    int stride = gridDim.x * blockDim.x;
    const int total = NNODES * CH / 4;
    const float4* h4 = (const float4*)g_h;
    float4* o4 = (float4*)out;
    for (int i = idx; i < total; i += stride) {
        int c = (i & 63) * 4;  // column of first element (CH/4 = 64)
        float4 h = h4[i];
        float4 o = o4[i];
        float4 sc = *(const float4*)&g_scale[c];
        float4 sh = *(const float4*)&g_shift[c];
        o4[i] = make_float4(fmaf(h.x, sc.x, sh.x) + o.x,
                            fmaf(h.y, sc.y, sh.y) + o.y,
                            fmaf(h.z, sc.z, sh.z) + o.z,
                            fmaf(h.w, sc.w, sh.w) + o.w);
    }
}

// ---------------------------------------------------------------------------
extern "C" void kernel_launch(void* const* d_in, const int* in_sizes, int n_in,
                              void* d_out, int out_size) {
    const float* x      = (const float*)d_in[0];
    const int*   ei     = (const int*)d_in[1];
    const float* ea     = (const float*)d_in[2];
    const float* W_edge = (const float*)d_in[3];
    const float* W_rel  = (const float*)d_in[4];
    const float* b_rel  = (const float*)d_in[5];
    const float* W_root = (const float*)d_in[6];
    const float* gamma  = (const float*)d_in[7];
    const float* beta   = (const float*)d_in[8];
    const float* W_res  = (const float*)d_in[9];
    int E = in_sizes[1] / 2;
    float* out = (float*)d_out;

    zero_kernel<<<256, 256>>>();
    edge_kernel<<<888, 128>>>(x, ei, ea, W_edge, E);
    dim3 g((NNODES + BM - 1) / BM, 8);
    node_gemm<<<g, 128>>>(x, W_rel, b_rel, W_root, W_res, out);
    bn_stats<<<1, 256>>>(gamma, beta);
    finalize<<<592, 256>>>(out);
}

// round 2
// speedup vs baseline: 2.0111x; 2.0111x over previous
#include <cuda_runtime.h>
#include <cstdint>

#define NNODES 20000
#define CH 256
#define ECH 64
#define MAXE 320000

// Scratch (allocation-free rule: __device__ globals)
__device__ float g_e[(size_t)MAXE * CH];      // projected edge features
__device__ float g_agg[NNODES * CH];
__device__ float g_h[NNODES * CH];
__device__ int   g_cnt[NNODES];
__device__ int   g_rowstart[NNODES + 1];
__device__ int   g_cursor[NNODES];
__device__ int2  g_csr[MAXE];                 // {edge_id, src}
__device__ float g_sum[CH];
__device__ float g_sumsq[CH];

typedef unsigned long long ull;

__device__ __forceinline__ ull f2fma(ull a, ull b, ull c) {
    ull d;
    asm("fma.rn.f32x2 %0, %1, %2, %3;" : "=l"(d) : "l"(a), "l"(b), "l"(c));
    return d;
}
__device__ __forceinline__ ull pack2(float v) {
    unsigned r = __float_as_uint(v);
    ull d;
    asm("mov.b64 %0, {%1, %2};" : "=l"(d) : "r"(r), "r"(r));
    return d;
}
__device__ __forceinline__ float2 unpack2(ull v) {
    unsigned lo, hi;
    asm("mov.b64 {%0, %1}, %2;" : "=r"(lo), "=r"(hi) : "l"(v));
    return make_float2(__uint_as_float(lo), __uint_as_float(hi));
}

// ---------------------------------------------------------------------------
// K0: zero counters + BN stat accumulators
// ---------------------------------------------------------------------------
__global__ void zero_kernel() {
    int idx = blockIdx.x * blockDim.x + threadIdx.x;
    if (idx < NNODES) g_cnt[idx] = 0;
    if (idx < CH) { g_sum[idx] = 0.f; g_sumsq[idx] = 0.f; }
}

// ---------------------------------------------------------------------------
// K1: degree histogram over dst
// ---------------------------------------------------------------------------
__global__ void hist_kernel(const int* __restrict__ ei, int E) {
    int e = blockIdx.x * blockDim.x + threadIdx.x;
    if (e < E) atomicAdd(&g_cnt[__ldg(&ei[E + e])], 1);
}

// ---------------------------------------------------------------------------
// K2: exclusive scan of degrees -> rowstart + cursor (single block, 256 thr)
// ---------------------------------------------------------------------------
__global__ void scan_kernel(int E) {
    __shared__ int sp[256];
    const int t = threadIdx.x;
    const int CHUNK = (NNODES + 255) / 256;   // 79
    int beg = t * CHUNK;
    int end = min(beg + CHUNK, NNODES);
    int mysum = 0;
    for (int i = beg; i < end; i++) mysum += g_cnt[i];
    sp[t] = mysum;
    __syncthreads();
#pragma unroll
    for (int off = 1; off < 256; off <<= 1) {
        int v = (t >= off) ? sp[t - off] : 0;
        __syncthreads();
        sp[t] += v;
        __syncthreads();
    }
    int running = sp[t] - mysum;  // exclusive prefix
    for (int i = beg; i < end; i++) {
        int c = g_cnt[i];
        g_rowstart[i] = running;
        g_cursor[i] = running;
        running += c;
    }
    if (t == 255) g_rowstart[NNODES] = E;
}

// ---------------------------------------------------------------------------
// K3: fill CSR: for each edge, slot into its dst row
// ---------------------------------------------------------------------------
__global__ void fill_kernel(const int* __restrict__ ei, int E) {
    int e = blockIdx.x * blockDim.x + threadIdx.x;
    if (e < E) {
        int dst = __ldg(&ei[E + e]);
        int src = __ldg(&ei[e]);
        int pos = atomicAdd(&g_cursor[dst], 1);
        g_csr[pos] = make_int2(e, src);
    }
}

// ---------------------------------------------------------------------------
// K4: e = edge_attr @ W_edge   [E x 64] x [64 x 256] -> g_e
// 128x128 block tile, BK=8, 256 threads, 8x8 thread tile (f32x2 pairs on N)
// ---------------------------------------------------------------------------
__global__ void __launch_bounds__(256, 2) egemm_kernel(
    const float* __restrict__ A, const float* __restrict__ B, int M)
{
    __shared__ float As[8][128];
    __shared__ float Bs[8][128];
    const int tid = threadIdx.x;
    const int tx = tid & 15;    // n group
    const int ty = tid >> 4;    // m group
    const int m0 = blockIdx.x * 128;
    const int n0 = blockIdx.y * 128;

    const int arow = tid >> 1;
    const int aq = (tid & 1) * 4;
    const int bk = tid >> 5;
    const int bn = (tid & 31) * 4;

    ull acc[8][4];
#pragma unroll
    for (int i = 0; i < 8; i++)
#pragma unroll
        for (int j = 0; j < 4; j++) acc[i][j] = 0;

    for (int k0 = 0; k0 < ECH; k0 += 8) {
        int row = m0 + arow;
        float4 av = make_float4(0.f, 0.f, 0.f, 0.f);
        if (row < M) av = __ldg((const float4*)(A + (size_t)row * ECH + k0 + aq));
        As[aq + 0][arow] = av.x; As[aq + 1][arow] = av.y;
        As[aq + 2][arow] = av.z; As[aq + 3][arow] = av.w;
        float4 bv = __ldg((const float4*)(B + (size_t)(k0 + bk) * CH + n0 + bn));
        *(float4*)&Bs[bk][bn] = bv;
        __syncthreads();
#pragma unroll
        for (int k = 0; k < 8; k++) {
            float4 alo = *(const float4*)&As[k][ty * 4];
            float4 ahi = *(const float4*)&As[k][ty * 4 + 64];
            ulonglong2 blo = *(const ulonglong2*)&Bs[k][tx * 4];
            ulonglong2 bhi = *(const ulonglong2*)&Bs[k][tx * 4 + 64];
            ull pa[8] = {pack2(alo.x), pack2(alo.y), pack2(alo.z), pack2(alo.w),
                         pack2(ahi.x), pack2(ahi.y), pack2(ahi.z), pack2(ahi.w)};
#pragma unroll
            for (int i = 0; i < 8; i++) {
                acc[i][0] = f2fma(pa[i], blo.x, acc[i][0]);
                acc[i][1] = f2fma(pa[i], blo.y, acc[i][1]);
                acc[i][2] = f2fma(pa[i], bhi.x, acc[i][2]);
                acc[i][3] = f2fma(pa[i], bhi.y, acc[i][3]);
            }
        }
        __syncthreads();
    }
#pragma unroll
    for (int i = 0; i < 8; i++) {
        int row = m0 + ty * 4 + (i < 4 ? i : 64 + (i - 4));
        if (row < M) {
            float2 v0 = unpack2(acc[i][0]);
            float2 v1 = unpack2(acc[i][1]);
            float2 v2 = unpack2(acc[i][2]);
            float2 v3 = unpack2(acc[i][3]);
            *(float4*)(g_e + (size_t)row * CH + n0 + tx * 4) =
                make_float4(v0.x, v0.y, v1.x, v1.y);
            *(float4*)(g_e + (size_t)row * CH + n0 + tx * 4 + 64) =
                make_float4(v2.x, v2.y, v3.x, v3.y);
        }
    }
}

// ---------------------------------------------------------------------------
// K5: gather-aggregate: agg[n] = sum_{e in row(n)} g_e[e] * x[src(e)]
// 256 threads, thread = channel; no atomics, plain stores.
// ---------------------------------------------------------------------------
__global__ void __launch_bounds__(256) agg_kernel(const float* __restrict__ x) {
    const int c = threadIdx.x;
    for (int n = blockIdx.x; n < NNODES; n += gridDim.x) {
        int beg = g_rowstart[n];
        int end = g_rowstart[n + 1];
        float a0 = 0.f, a1 = 0.f, a2 = 0.f, a3 = 0.f;
        int i = beg;
        for (; i + 4 <= end; i += 4) {
            int2 e0 = __ldg(&g_csr[i + 0]);
            int2 e1 = __ldg(&g_csr[i + 1]);
            int2 e2 = __ldg(&g_csr[i + 2]);
            int2 e3 = __ldg(&g_csr[i + 3]);
            float ev0 = __ldg(&g_e[(size_t)e0.x * CH + c]);
            float xv0 = __ldg(&x[(size_t)e0.y * CH + c]);
            float ev1 = __ldg(&g_e[(size_t)e1.x * CH + c]);
            float xv1 = __ldg(&x[(size_t)e1.y * CH + c]);
            float ev2 = __ldg(&g_e[(size_t)e2.x * CH + c]);
            float xv2 = __ldg(&x[(size_t)e2.y * CH + c]);
            float ev3 = __ldg(&g_e[(size_t)e3.x * CH + c]);
            float xv3 = __ldg(&x[(size_t)e3.y * CH + c]);
            a0 = fmaf(ev0, xv0, a0);
            a1 = fmaf(ev1, xv1, a1);
            a2 = fmaf(ev2, xv2, a2);
            a3 = fmaf(ev3, xv3, a3);
        }
        for (; i < end; i++) {
            int2 e0 = __ldg(&g_csr[i]);
            float ev = __ldg(&g_e[(size_t)e0.x * CH + c]);
            float xv = __ldg(&x[(size_t)e0.y * CH + c]);
            a0 = fmaf(ev, xv, a0);
        }
        g_agg[(size_t)n * CH + c] = (a0 + a1) + (a2 + a3);
    }
}

// ---------------------------------------------------------------------------
// K6: node GEMMs. Virtual output [N, 512]:
//   yb 0..1: h = relu(agg@W_rel + b_rel + x@W_root) -> g_h + BN stats
//   yb 2..3: res = x@W_res -> d_out
// 128x128 tile, BK=8, 256 threads, 8x8 thread tile.
// ---------------------------------------------------------------------------
__global__ void __launch_bounds__(256, 2) node_gemm(
    const float* __restrict__ x,
    const float* __restrict__ W_rel, const float* __restrict__ b_rel,
    const float* __restrict__ W_root, const float* __restrict__ W_res,
    float* __restrict__ out)
{
    __shared__ float As[8][128];
    __shared__ float Bs[8][128];
    const int tid = threadIdx.x;
    const int tx = tid & 15;
    const int ty = tid >> 4;
    const int m0 = blockIdx.x * 128;
    const int yb = blockIdx.y;
    const bool isH = (yb < 2);
    const int n0 = (isH ? yb : yb - 2) * 128;

    const int arow = tid >> 1;
    const int aq = (tid & 1) * 4;
    const int bk = tid >> 5;
    const int bn = (tid & 31) * 4;

    ull acc[8][4];
#pragma unroll
    for (int i = 0; i < 8; i++)
#pragma unroll
        for (int j = 0; j < 4; j++) acc[i][j] = 0;

    const int nph = isH ? 2 : 1;
    for (int p = 0; p < nph; p++) {
        const float* A = (isH && p == 0) ? g_agg : x;
        const float* B = isH ? (p == 0 ? W_rel : W_root) : W_res;
        for (int k0 = 0; k0 < CH; k0 += 8) {
            int row = m0 + arow;
            float4 av = make_float4(0.f, 0.f, 0.f, 0.f);
            if (row < NNODES) av = __ldg((const float4*)(A + (size_t)row * CH + k0 + aq));
            As[aq + 0][arow] = av.x; As[aq + 1][arow] = av.y;
            As[aq + 2][arow] = av.z; As[aq + 3][arow] = av.w;
            float4 bv = __ldg((const float4*)(B + (size_t)(k0 + bk) * CH + n0 + bn));
            *(float4*)&Bs[bk][bn] = bv;
            __syncthreads();
#pragma unroll
            for (int k = 0; k < 8; k++) {
                float4 alo = *(const float4*)&As[k][ty * 4];
                float4 ahi = *(const float4*)&As[k][ty * 4 + 64];
                ulonglong2 blo = *(const ulonglong2*)&Bs[k][tx * 4];
                ulonglong2 bhi = *(const ulonglong2*)&Bs[k][tx * 4 + 64];
                ull pa[8] = {pack2(alo.x), pack2(alo.y), pack2(alo.z), pack2(alo.w),
                             pack2(ahi.x), pack2(ahi.y), pack2(ahi.z), pack2(ahi.w)};
#pragma unroll
                for (int i = 0; i < 8; i++) {
                    acc[i][0] = f2fma(pa[i], blo.x, acc[i][0]);
                    acc[i][1] = f2fma(pa[i], blo.y, acc[i][1]);
                    acc[i][2] = f2fma(pa[i], bhi.x, acc[i][2]);
                    acc[i][3] = f2fma(pa[i], bhi.y, acc[i][3]);
                }
            }
            __syncthreads();
        }
    }

    const int clo = n0 + tx * 4;
    const int chi = clo + 64;
    if (isH) {
        float4 blo4 = __ldg((const float4*)(b_rel + clo));
        float4 bhi4 = __ldg((const float4*)(b_rel + chi));
        float cs[8] = {0.f, 0.f, 0.f, 0.f, 0.f, 0.f, 0.f, 0.f};
        float cq[8] = {0.f, 0.f, 0.f, 0.f, 0.f, 0.f, 0.f, 0.f};
#pragma unroll
        for (int i = 0; i < 8; i++) {
            int row = m0 + ty * 4 + (i < 4 ? i : 64 + (i - 4));
            if (row < NNODES) {
                float2 v0 = unpack2(acc[i][0]);
                float2 v1 = unpack2(acc[i][1]);
                float2 v2 = unpack2(acc[i][2]);
                float2 v3 = unpack2(acc[i][3]);
                float h0 = fmaxf(v0.x + blo4.x, 0.f);
                float h1 = fmaxf(v0.y + blo4.y, 0.f);
                float h2 = fmaxf(v1.x + blo4.z, 0.f);
                float h3 = fmaxf(v1.y + blo4.w, 0.f);
                float h4 = fmaxf(v2.x + bhi4.x, 0.f);
                float h5 = fmaxf(v2.y + bhi4.y, 0.f);
                float h6 = fmaxf(v3.x + bhi4.z, 0.f);
                float h7 = fmaxf(v3.y + bhi4.w, 0.f);
                *(float4*)(g_h + (size_t)row * CH + clo) = make_float4(h0, h1, h2, h3);
                *(float4*)(g_h + (size_t)row * CH + chi) = make_float4(h4, h5, h6, h7);
                cs[0] += h0; cs[1] += h1; cs[2] += h2; cs[3] += h3;
                cs[4] += h4; cs[5] += h5; cs[6] += h6; cs[7] += h7;
                cq[0] += h0 * h0; cq[1] += h1 * h1; cq[2] += h2 * h2; cq[3] += h3 * h3;
                cq[4] += h4 * h4; cq[5] += h5 * h5; cq[6] += h6 * h6; cq[7] += h7 * h7;
            }
        }
#pragma unroll
        for (int j = 0; j < 4; j++) {
            atomicAdd(&g_sum[clo + j], cs[j]);
            atomicAdd(&g_sum[chi + j], cs[4 + j]);
            atomicAdd(&g_sumsq[clo + j], cq[j]);
            atomicAdd(&g_sumsq[chi + j], cq[4 + j]);
        }
    } else {
#pragma unroll
        for (int i = 0; i < 8; i++) {
            int row = m0 + ty * 4 + (i < 4 ? i : 64 + (i - 4));
            if (row < NNODES) {
                float2 v0 = unpack2(acc[i][0]);
                float2 v1 = unpack2(acc[i][1]);
                float2 v2 = unpack2(acc[i][2]);
                float2 v3 = unpack2(acc[i][3]);
                *(float4*)(out + (size_t)row * CH + clo) = make_float4(v0.x, v0.y, v1.x, v1.y);
                *(float4*)(out + (size_t)row * CH + chi) = make_float4(v2.x, v2.y, v3.x, v3.y);
            }
        }
    }
}

// ---------------------------------------------------------------------------
// K7: finalize: out = h * scale + shift + res (scale/shift from BN stats)
// ---------------------------------------------------------------------------
__global__ void __launch_bounds__(256) finalize(
    const float* __restrict__ gamma, const float* __restrict__ beta,
    float* __restrict__ out)
{
    __shared__ float ssc[CH], ssh[CH];
    int t = threadIdx.x;
    {
        float m = g_sum[t] * (1.0f / NNODES);
        float var = g_sumsq[t] * (1.0f / NNODES) - m * m;
        float is = rsqrtf(var + 1e-5f);
        float sc = is * __ldg(&gamma[t]);
        ssc[t] = sc;
        ssh[t] = __ldg(&beta[t]) - m * sc;
    }
    __syncthreads();
    int idx = blockIdx.x * blockDim.x + t;
    int stride = gridDim.x * blockDim.x;
    const int total = NNODES * CH / 4;
    const float4* h4 = (const float4*)g_h;
    float4* o4 = (float4*)out;
    for (int i = idx; i < total; i += stride) {
        int c = (i & 63) * 4;
        float4 h = h4[i];
        float4 o = o4[i];
        float4 sc = *(const float4*)&ssc[c];
        float4 sh = *(const float4*)&ssh[c];
        o4[i] = make_float4(fmaf(h.x, sc.x, sh.x) + o.x,
                            fmaf(h.y, sc.y, sh.y) + o.y,
                            fmaf(h.z, sc.z, sh.z) + o.z,
                            fmaf(h.w, sc.w, sh.w) + o.w);
    }
}

// ---------------------------------------------------------------------------
extern "C" void kernel_launch(void* const* d_in, const int* in_sizes, int n_in,
                              void* d_out, int out_size) {
    const float* x      = (const float*)d_in[0];
    const int*   ei     = (const int*)d_in[1];
    const float* ea     = (const float*)d_in[2];
    const float* W_edge = (const float*)d_in[3];
    const float* W_rel  = (const float*)d_in[4];
    const float* b_rel  = (const float*)d_in[5];
    const float* W_root = (const float*)d_in[6];
    const float* gamma  = (const float*)d_in[7];
    const float* beta   = (const float*)d_in[8];
    const float* W_res  = (const float*)d_in[9];
    int E = in_sizes[1] / 2;
    float* out = (float*)d_out;

    zero_kernel<<<(NNODES + 255) / 256, 256>>>();
    hist_kernel<<<(E + 255) / 256, 256>>>(ei, E);
    scan_kernel<<<1, 256>>>(E);
    fill_kernel<<<(E + 255) / 256, 256>>>(ei, E);
    dim3 ge((E + 127) / 128, 2);
    egemm_kernel<<<ge, 256>>>(ea, W_edge, E);
    agg_kernel<<<592, 256>>>(x);
    dim3 gn((NNODES + 127) / 128, 4);
    node_gemm<<<gn, 256>>>(x, W_rel, b_rel, W_root, W_res, out);
    finalize<<<592, 256>>>(gamma, beta, out);
}

// round 5
// speedup vs baseline: 2.4135x; 1.2001x over previous
#include <cuda_runtime.h>
#include <cuda_bf16.h>
#include <cstdint>

#define NNODES 20000
#define CH 256
#define ECH 64
#define MAXE 320000

typedef unsigned long long ull;

// ---------------- scratch (__device__ globals; no allocation) ----------------
__device__ float g_e[(size_t)MAXE * CH];
__device__ float g_agg[NNODES * CH];
__device__ float g_h[NNODES * CH];
__device__ int   g_cnt[NNODES];
__device__ int   g_rowstart[NNODES + 1];
__device__ int   g_cursor[NNODES];
__device__ int2  g_csr[MAXE];
__device__ float g_sum[CH];
__device__ float g_sumsq[CH];
__device__ __nv_bfloat16 g_WTe_hi[CH * ECH], g_WTe_lo[CH * ECH];
__device__ __nv_bfloat16 g_WTrel_hi[CH * CH], g_WTrel_lo[CH * CH];
__device__ __nv_bfloat16 g_WTroot_hi[CH * CH], g_WTroot_lo[CH * CH];
__device__ __nv_bfloat16 g_WTres_hi[CH * CH], g_WTres_lo[CH * CH];

// ---------------- helpers ----------------
__device__ __forceinline__ uint32_t smem_u32(const void* p) {
    uint32_t a;
    asm("{ .reg .u64 t; cvta.to.shared.u64 t, %1; cvt.u32.u64 %0, t; }" : "=r"(a) : "l"(p));
    return a;
}
#define SWZ(off) ((off) ^ (((off) >> 3) & 0x70))

__device__ __forceinline__ void ldsm_x4(uint32_t* r, uint32_t addr) {
    asm volatile("ldmatrix.sync.aligned.m8n8.x4.shared.b16 {%0,%1,%2,%3}, [%4];"
        : "=r"(r[0]), "=r"(r[1]), "=r"(r[2]), "=r"(r[3]) : "r"(addr));
}
// NON-trans: B stored [n][k] (k contiguous) -> correct col-fragment for row.col mma
__device__ __forceinline__ void ldsm_x2(uint32_t* r, uint32_t addr) {
    asm volatile("ldmatrix.sync.aligned.m8n8.x2.shared.b16 {%0,%1}, [%2];"
        : "=r"(r[0]), "=r"(r[1]) : "r"(addr));
}
__device__ __forceinline__ void mma16816(float* c, const uint32_t* a, const uint32_t* b) {
    asm volatile("mma.sync.aligned.m16n8k16.row.col.f32.bf16.bf16.f32 "
        "{%0,%1,%2,%3}, {%4,%5,%6,%7}, {%8,%9}, {%0,%1,%2,%3};"
        : "+f"(c[0]), "+f"(c[1]), "+f"(c[2]), "+f"(c[3])
        : "r"(a[0]), "r"(a[1]), "r"(a[2]), "r"(a[3]), "r"(b[0]), "r"(b[1]));
}
// split a float4 into hi/lo bf16x4 packed as 8 bytes each
__device__ __forceinline__ void split4(float4 v, ull& hb, ull& lb) {
    __nv_bfloat16 h0 = __float2bfloat16(v.x), h1 = __float2bfloat16(v.y);
    __nv_bfloat16 h2 = __float2bfloat16(v.z), h3 = __float2bfloat16(v.w);
    __nv_bfloat16 l0 = __float2bfloat16(v.x - __bfloat162float(h0));
    __nv_bfloat16 l1 = __float2bfloat16(v.y - __bfloat162float(h1));
    __nv_bfloat16 l2 = __float2bfloat16(v.z - __bfloat162float(h2));
    __nv_bfloat16 l3 = __float2bfloat16(v.w - __bfloat162float(h3));
    hb = (ull)__bfloat16_as_ushort(h0) | ((ull)__bfloat16_as_ushort(h1) << 16) |
         ((ull)__bfloat16_as_ushort(h2) << 32) | ((ull)__bfloat16_as_ushort(h3) << 48);
    lb = (ull)__bfloat16_as_ushort(l0) | ((ull)__bfloat16_as_ushort(l1) << 16) |
         ((ull)__bfloat16_as_ushort(l2) << 32) | ((ull)__bfloat16_as_ushort(l3) << 48);
}

// ---------------------------------------------------------------------------
// K0: zero counters + BN stat accumulators
// ---------------------------------------------------------------------------
__global__ void zero_kernel() {
    int idx = blockIdx.x * blockDim.x + threadIdx.x;
    if (idx < NNODES) g_cnt[idx] = 0;
    if (idx < CH) { g_sum[idx] = 0.f; g_sumsq[idx] = 0.f; }
}

// ---------------------------------------------------------------------------
// K1: weight transpose + bf16 hi/lo split. grid 256 (n), block 256 (k)
// ---------------------------------------------------------------------------
__global__ void __launch_bounds__(256) wprep_kernel(
    const float* __restrict__ We, const float* __restrict__ Wrel,
    const float* __restrict__ Wroot, const float* __restrict__ Wres)
{
    int n = blockIdx.x;
    int k = threadIdx.x;
    if (k < ECH) {
        float v = __ldg(&We[(size_t)k * CH + n]);
        __nv_bfloat16 h = __float2bfloat16(v);
        g_WTe_hi[n * ECH + k] = h;
        g_WTe_lo[n * ECH + k] = __float2bfloat16(v - __bfloat162float(h));
    }
    {
        float v = __ldg(&Wrel[(size_t)k * CH + n]);
        __nv_bfloat16 h = __float2bfloat16(v);
        g_WTrel_hi[n * CH + k] = h;
        g_WTrel_lo[n * CH + k] = __float2bfloat16(v - __bfloat162float(h));
    }
    {
        float v = __ldg(&Wroot[(size_t)k * CH + n]);
        __nv_bfloat16 h = __float2bfloat16(v);
        g_WTroot_hi[n * CH + k] = h;
        g_WTroot_lo[n * CH + k] = __float2bfloat16(v - __bfloat162float(h));
    }
    {
        float v = __ldg(&Wres[(size_t)k * CH + n]);
        __nv_bfloat16 h = __float2bfloat16(v);
        g_WTres_hi[n * CH + k] = h;
        g_WTres_lo[n * CH + k] = __float2bfloat16(v - __bfloat162float(h));
    }
}

// ---------------------------------------------------------------------------
// K2: degree histogram / scan / fill (CSR build)
// ---------------------------------------------------------------------------
__global__ void hist_kernel(const int* __restrict__ ei, int E) {
    int e = blockIdx.x * blockDim.x + threadIdx.x;
    if (e < E) atomicAdd(&g_cnt[__ldg(&ei[E + e])], 1);
}
__global__ void scan_kernel(int E) {
    __shared__ int sp[256];
    const int t = threadIdx.x;
    const int CHUNK = (NNODES + 255) / 256;
    int beg = t * CHUNK;
    int end = min(beg + CHUNK, NNODES);
    int mysum = 0;
    for (int i = beg; i < end; i++) mysum += g_cnt[i];
    sp[t] = mysum;
    __syncthreads();
#pragma unroll
    for (int off = 1; off < 256; off <<= 1) {
        int v = (t >= off) ? sp[t - off] : 0;
        __syncthreads();
        sp[t] += v;
        __syncthreads();
    }
    int running = sp[t] - mysum;
    for (int i = beg; i < end; i++) {
        int c = g_cnt[i];
        g_rowstart[i] = running;
        g_cursor[i] = running;
        running += c;
    }
    if (t == 255) g_rowstart[NNODES] = E;
}
__global__ void fill_kernel(const int* __restrict__ ei, int E) {
    int e = blockIdx.x * blockDim.x + threadIdx.x;
    if (e < E) {
        int dst = __ldg(&ei[E + e]);
        int src = __ldg(&ei[e]);
        int pos = atomicAdd(&g_cursor[dst], 1);
        g_csr[pos] = make_int2(e, src);
    }
}

// ---------------------------------------------------------------------------
// K3: egemm via HMMA: g_e = ea @ We^T   [E x 64] x [64 x 256]
// CTA tile 128m x 256n x K64; 512 thr = 16 warps (2m x 8n), warp 64x32.
// smem: Ah 16K | Al 16K | Bh 32K | Bl 32K  (96KB, SW128-style swizzle)
// ---------------------------------------------------------------------------
__global__ void __launch_bounds__(512, 1) egemm_mma(
    const float* __restrict__ ea, int E)
{
    extern __shared__ char dsm[];
    char* base = (char*)(((uintptr_t)dsm + 1023) & ~(uintptr_t)1023);
    char* Ah = base;
    char* Al = base + 16384;
    char* Bh = base + 32768;
    char* Bl = base + 65536;

    const int tid = threadIdx.x;
    const int lane = tid & 31;
    const int wid = tid >> 5;
    const int wm = wid >> 3;      // 0..1  -> m offset 64*wm
    const int wn = wid & 7;       // 0..7  -> n offset 32*wn
    const int m0 = blockIdx.x * 128;

    // fill A (128 rows x 64 k fp32 -> hi/lo bf16)
    for (int idx = tid; idx < 2048; idx += 512) {
        int row = idx >> 4, q = idx & 15;
        int e = m0 + row;
        float4 v = make_float4(0.f, 0.f, 0.f, 0.f);
        if (e < E) v = __ldg((const float4*)(ea + (size_t)e * ECH) + q);
        ull hb, lb; split4(v, hb, lb);
        uint32_t off = SWZ(row * 128 + q * 8);
        *(ull*)(Ah + off) = hb;
        *(ull*)(Al + off) = lb;
    }
    // fill B (WTe [256 n][64 k] bf16 hi/lo)
    {
        const uint4* sh = (const uint4*)g_WTe_hi;
        const uint4* sl = (const uint4*)g_WTe_lo;
        for (int idx = tid; idx < 2048; idx += 512) {
            int n = idx >> 3, q = idx & 7;
            uint32_t off = SWZ(n * 128 + q * 16);
            *(uint4*)(Bh + off) = __ldg(&sh[idx]);
            *(uint4*)(Bl + off) = __ldg(&sl[idx]);
        }
    }
    __syncthreads();

    float acc[4][4][4];
#pragma unroll
    for (int i = 0; i < 4; i++)
#pragma unroll
        for (int j = 0; j < 4; j++)
#pragma unroll
            for (int k = 0; k < 4; k++) acc[i][j][k] = 0.f;

    const uint32_t ah = smem_u32(Ah), al = smem_u32(Al);
    const uint32_t bh = smem_u32(Bh), bl = smem_u32(Bl);
    const uint32_t abase[3] = {ah, ah, al};
    const uint32_t bbase[3] = {bh, bl, bh};

#pragma unroll
    for (int p = 0; p < 3; p++) {
#pragma unroll
        for (int ks = 0; ks < 4; ks++) {
            int ko = ks * 32;
            uint32_t af[4][4], bf[4][2];
#pragma unroll
            for (int i = 0; i < 4; i++)
                ldsm_x4(af[i], abase[p] +
                    SWZ((wm * 64 + i * 16 + (lane & 15)) * 128 + ko + (lane >> 4) * 16));
#pragma unroll
            for (int j = 0; j < 4; j++)
                ldsm_x2(bf[j], bbase[p] +
                    SWZ((wn * 32 + j * 8 + (lane & 7)) * 128 + ko + ((lane >> 3) & 1) * 16));
#pragma unroll
            for (int i = 0; i < 4; i++)
#pragma unroll
                for (int j = 0; j < 4; j++) mma16816(acc[i][j], af[i], bf[j]);
        }
    }

    // epilogue -> g_e fp32
    const int g = lane >> 2, tig = lane & 3;
#pragma unroll
    for (int i = 0; i < 4; i++) {
        int r0 = m0 + wm * 64 + i * 16 + g;
#pragma unroll
        for (int j = 0; j < 4; j++) {
            int c = wn * 32 + j * 8 + 2 * tig;
            if (r0 < E)
                *(float2*)(g_e + (size_t)r0 * CH + c) = make_float2(acc[i][j][0], acc[i][j][1]);
            if (r0 + 8 < E)
                *(float2*)(g_e + (size_t)(r0 + 8) * CH + c) = make_float2(acc[i][j][2], acc[i][j][3]);
        }
    }
}

// ---------------------------------------------------------------------------
// K4: gather-aggregate: agg[n] = sum_{e in row(n)} g_e[e] * x[src(e)]
// ---------------------------------------------------------------------------
__global__ void __launch_bounds__(256) agg_kernel(const float* __restrict__ x) {
    const int c = threadIdx.x;
    for (int n = blockIdx.x; n < NNODES; n += gridDim.x) {
        int beg = g_rowstart[n];
        int end = g_rowstart[n + 1];
        float a0 = 0.f, a1 = 0.f, a2 = 0.f, a3 = 0.f;
        int i = beg;
        for (; i + 4 <= end; i += 4) {
            int2 e0 = __ldg(&g_csr[i + 0]);
            int2 e1 = __ldg(&g_csr[i + 1]);
            int2 e2 = __ldg(&g_csr[i + 2]);
            int2 e3 = __ldg(&g_csr[i + 3]);
            float ev0 = __ldg(&g_e[(size_t)e0.x * CH + c]);
            float xv0 = __ldg(&x[(size_t)e0.y * CH + c]);
            float ev1 = __ldg(&g_e[(size_t)e1.x * CH + c]);
            float xv1 = __ldg(&x[(size_t)e1.y * CH + c]);
            float ev2 = __ldg(&g_e[(size_t)e2.x * CH + c]);
            float xv2 = __ldg(&x[(size_t)e2.y * CH + c]);
            float ev3 = __ldg(&g_e[(size_t)e3.x * CH + c]);
            float xv3 = __ldg(&x[(size_t)e3.y * CH + c]);
            a0 = fmaf(ev0, xv0, a0);
            a1 = fmaf(ev1, xv1, a1);
            a2 = fmaf(ev2, xv2, a2);
            a3 = fmaf(ev3, xv3, a3);
        }
        for (; i < end; i++) {
            int2 e0 = __ldg(&g_csr[i]);
            a0 = fmaf(__ldg(&g_e[(size_t)e0.x * CH + c]),
                      __ldg(&x[(size_t)e0.y * CH + c]), a0);
        }
        g_agg[(size_t)n * CH + c] = (a0 + a1) + (a2 + a3);
    }
}

// ---------------------------------------------------------------------------
// K5: node HMMA. grid (ceil(N/128), 2):
//  yb0: h = relu(agg@Wrel + x@Wroot + b) -> g_h
//  yb1: res = x@Wres -> out
// K processed in chunks of 64; register fp32 accumulators carry across chunks.
// smem: Ah 16K | Al 16K | Bh 32K | Bl 32K
// ---------------------------------------------------------------------------
__global__ void __launch_bounds__(512, 1) node_mma(
    const float* __restrict__ x, const float* __restrict__ b_rel,
    float* __restrict__ out)
{
    extern __shared__ char dsm[];
    char* base = (char*)(((uintptr_t)dsm + 1023) & ~(uintptr_t)1023);
    char* Ah = base;
    char* Al = base + 16384;
    char* Bh = base + 32768;
    char* Bl = base + 65536;

    const int tid = threadIdx.x;
    const int lane = tid & 31;
    const int wid = tid >> 5;
    const int wm = wid >> 3;
    const int wn = wid & 7;
    const int m0 = blockIdx.x * 128;
    const int yb = blockIdx.y;

    float acc[4][4][4];
#pragma unroll
    for (int i = 0; i < 4; i++)
#pragma unroll
        for (int j = 0; j < 4; j++)
#pragma unroll
            for (int k = 0; k < 4; k++) acc[i][j][k] = 0.f;

    const uint32_t aha = smem_u32(Ah), ala = smem_u32(Al);
    const uint32_t bha = smem_u32(Bh), bla = smem_u32(Bl);
    const uint32_t abase[3] = {aha, aha, ala};
    const uint32_t bbase[3] = {bha, bla, bha};

    const int nsrc = (yb == 0) ? 2 : 1;
    for (int s = 0; s < nsrc; s++) {
        const float* A = (yb == 0) ? (s == 0 ? g_agg : x) : x;
        const __nv_bfloat16* WH = (yb == 0) ? (s == 0 ? g_WTrel_hi : g_WTroot_hi) : g_WTres_hi;
        const __nv_bfloat16* WL = (yb == 0) ? (s == 0 ? g_WTrel_lo : g_WTroot_lo) : g_WTres_lo;

        for (int kc = 0; kc < 4; kc++) {
            int k0 = kc * 64;
            // fill A chunk 128 x 64
            for (int idx = tid; idx < 2048; idx += 512) {
                int row = idx >> 4, q = idx & 15;
                int r = m0 + row;
                float4 v = make_float4(0.f, 0.f, 0.f, 0.f);
                if (r < NNODES)
                    v = __ldg((const float4*)(A + (size_t)r * CH + k0) + q);
                ull hb, lb; split4(v, hb, lb);
                uint32_t off = SWZ(row * 128 + q * 8);
                *(ull*)(Ah + off) = hb;
                *(ull*)(Al + off) = lb;
            }
            // fill B chunk 256 x 64
            {
                const uint4* sh = (const uint4*)WH;
                const uint4* sl = (const uint4*)WL;
                int kq0 = k0 >> 3;
                for (int idx = tid; idx < 2048; idx += 512) {
                    int n = idx >> 3, q = idx & 7;
                    uint32_t off = SWZ(n * 128 + q * 16);
                    *(uint4*)(Bh + off) = __ldg(&sh[n * 32 + kq0 + q]);
                    *(uint4*)(Bl + off) = __ldg(&sl[n * 32 + kq0 + q]);
                }
            }
            __syncthreads();
#pragma unroll
            for (int p = 0; p < 3; p++) {
#pragma unroll
                for (int ks = 0; ks < 4; ks++) {
                    int ko = ks * 32;
                    uint32_t af[4][4], bf[4][2];
#pragma unroll
                    for (int i = 0; i < 4; i++)
                        ldsm_x4(af[i], abase[p] +
                            SWZ((wm * 64 + i * 16 + (lane & 15)) * 128 + ko + (lane >> 4) * 16));
#pragma unroll
                    for (int j = 0; j < 4; j++)
                        ldsm_x2(bf[j], bbase[p] +
                            SWZ((wn * 32 + j * 8 + (lane & 7)) * 128 + ko + ((lane >> 3) & 1) * 16));
#pragma unroll
                    for (int i = 0; i < 4; i++)
#pragma unroll
                        for (int j = 0; j < 4; j++) mma16816(acc[i][j], af[i], bf[j]);
                }
            }
            __syncthreads();
        }
    }

    // epilogue
    const int g = lane >> 2, tig = lane & 3;
    if (yb == 0) {
#pragma unroll
        for (int j = 0; j < 4; j++) {
            int c = wn * 32 + j * 8 + 2 * tig;
            float2 b = *(const float2*)(b_rel + c);
#pragma unroll
            for (int i = 0; i < 4; i++) {
                int r0 = m0 + wm * 64 + i * 16 + g;
                if (r0 < NNODES) {
                    float2 v = make_float2(fmaxf(acc[i][j][0] + b.x, 0.f),
                                           fmaxf(acc[i][j][1] + b.y, 0.f));
                    *(float2*)(g_h + (size_t)r0 * CH + c) = v;
                }
                if (r0 + 8 < NNODES) {
                    float2 v = make_float2(fmaxf(acc[i][j][2] + b.x, 0.f),
                                           fmaxf(acc[i][j][3] + b.y, 0.f));
                    *(float2*)(g_h + (size_t)(r0 + 8) * CH + c) = v;
                }
            }
        }
    } else {
#pragma unroll
        for (int j = 0; j < 4; j++) {
            int c = wn * 32 + j * 8 + 2 * tig;
#pragma unroll
            for (int i = 0; i < 4; i++) {
                int r0 = m0 + wm * 64 + i * 16 + g;
                if (r0 < NNODES)
                    *(float2*)(out + (size_t)r0 * CH + c) = make_float2(acc[i][j][0], acc[i][j][1]);
                if (r0 + 8 < NNODES)
                    *(float2*)(out + (size_t)(r0 + 8) * CH + c) = make_float2(acc[i][j][2], acc[i][j][3]);
            }
        }
    }
}

// ---------------------------------------------------------------------------
// K6: BN column sums over g_h
// ---------------------------------------------------------------------------
__global__ void __launch_bounds__(256) stats_kernel() {
    int c = threadIdx.x;
    float s = 0.f, q = 0.f;
    for (int r = blockIdx.x; r < NNODES; r += gridDim.x) {
        float v = g_h[(size_t)r * CH + c];
        s += v;
        q += v * v;
    }
    atomicAdd(&g_sum[c], s);
    atomicAdd(&g_sumsq[c], q);
}

// ---------------------------------------------------------------------------
// K7: finalize: out = h*scale + shift + res  (res already in out)
// ---------------------------------------------------------------------------
__global__ void __launch_bounds__(256) finalize(
    const float* __restrict__ gamma, const float* __restrict__ beta,
    float* __restrict__ out)
{
    __shared__ float ssc[CH], ssh[CH];
    int t = threadIdx.x;
    {
        float m = g_sum[t] * (1.0f / NNODES);
        float var = g_sumsq[t] * (1.0f / NNODES) - m * m;
        float is = rsqrtf(var + 1e-5f);
        float sc = is * __ldg(&gamma[t]);
        ssc[t] = sc;
        ssh[t] = __ldg(&beta[t]) - m * sc;
    }
    __syncthreads();
    int idx = blockIdx.x * blockDim.x + t;
    int stride = gridDim.x * blockDim.x;
    const int total = NNODES * CH / 4;
    const float4* h4 = (const float4*)g_h;
    float4* o4 = (float4*)out;
    for (int i = idx; i < total; i += stride) {
        int c = (i & 63) * 4;
        float4 h = h4[i];
        float4 o = o4[i];
        float4 sc = *(const float4*)&ssc[c];
        float4 sh = *(const float4*)&ssh[c];
        o4[i] = make_float4(fmaf(h.x, sc.x, sh.x) + o.x,
                            fmaf(h.y, sc.y, sh.y) + o.y,
                            fmaf(h.z, sc.z, sh.z) + o.z,
                            fmaf(h.w, sc.w, sh.w) + o.w);
    }
}

// ---------------------------------------------------------------------------
extern "C" void kernel_launch(void* const* d_in, const int* in_sizes, int n_in,
                              void* d_out, int out_size) {
    const float* x      = (const float*)d_in[0];
    const int*   ei     = (const int*)d_in[1];
    const float* ea     = (const float*)d_in[2];
    const float* W_edge = (const float*)d_in[3];
    const float* W_rel  = (const float*)d_in[4];
    const float* b_rel  = (const float*)d_in[5];
    const float* W_root = (const float*)d_in[6];
    const float* gamma  = (const float*)d_in[7];
    const float* beta   = (const float*)d_in[8];
    const float* W_res  = (const float*)d_in[9];
    int E = in_sizes[1] / 2;
    float* out = (float*)d_out;

    const int GEMM_SMEM = 98304 + 1024;
    cudaFuncSetAttribute(egemm_mma, cudaFuncAttributeMaxDynamicSharedMemorySize, GEMM_SMEM);
    cudaFuncSetAttribute(node_mma, cudaFuncAttributeMaxDynamicSharedMemorySize, GEMM_SMEM);

    zero_kernel<<<(NNODES + 255) / 256, 256>>>();
    wprep_kernel<<<256, 256>>>(W_edge, W_rel, W_root, W_res);
    hist_kernel<<<(E + 255) / 256, 256>>>(ei, E);
    scan_kernel<<<1, 256>>>(E);
    fill_kernel<<<(E + 255) / 256, 256>>>(ei, E);
    egemm_mma<<<(E + 127) / 128, 512, GEMM_SMEM>>>(ea, E);
    agg_kernel<<<592, 256>>>(x);
    dim3 gn((NNODES + 127) / 128, 2);
    node_mma<<<gn, 512, GEMM_SMEM>>>(x, b_rel, out);
    stats_kernel<<<160, 256>>>();
    finalize<<<592, 256>>>(gamma, beta, out);
}

// round 6
// speedup vs baseline: 2.9527x; 1.2234x over previous
#include <cuda_runtime.h>
#include <cuda_bf16.h>
#include <cstdint>

#define NNODES 20000
#define CH 256
#define ECH 64
#define MAXE 320000

typedef unsigned long long ull;

// ---------------- scratch (__device__ globals; no allocation) ----------------
__device__ float g_e[(size_t)MAXE * CH];
__device__ float g_h[NNODES * CH];
__device__ int   g_cnt[NNODES];
__device__ int   g_rowstart[NNODES + 1];
__device__ int   g_cursor[NNODES];
__device__ int2  g_csr[MAXE];
__device__ float g_sum[CH];
__device__ float g_sumsq[CH];
// pre-split bf16 operands (16B aligned for cp.async)
__device__ __align__(16) __nv_bfloat16 g_ea_hi[(size_t)MAXE * ECH], g_ea_lo[(size_t)MAXE * ECH];
__device__ __align__(16) __nv_bfloat16 g_x_hi[NNODES * CH], g_x_lo[NNODES * CH];
__device__ __align__(16) __nv_bfloat16 g_agg_hi[NNODES * CH], g_agg_lo[NNODES * CH];
__device__ __align__(16) __nv_bfloat16 g_WTe_hi[CH * ECH], g_WTe_lo[CH * ECH];
__device__ __align__(16) __nv_bfloat16 g_WTrel_hi[CH * CH], g_WTrel_lo[CH * CH];
__device__ __align__(16) __nv_bfloat16 g_WTroot_hi[CH * CH], g_WTroot_lo[CH * CH];
__device__ __align__(16) __nv_bfloat16 g_WTres_hi[CH * CH], g_WTres_lo[CH * CH];

// ---------------- helpers ----------------
__device__ __forceinline__ uint32_t smem_u32(const void* p) {
    uint32_t a;
    asm("{ .reg .u64 t; cvta.to.shared.u64 t, %1; cvt.u32.u64 %0, t; }" : "=r"(a) : "l"(p));
    return a;
}
#define SWZ(off) ((off) ^ (((off) >> 3) & 0x70))

__device__ __forceinline__ void cpa16(uint32_t dst, const void* src, int pred16) {
    asm volatile("cp.async.cg.shared.global [%0], [%1], 16, %2;"
                 :: "r"(dst), "l"(src), "r"(pred16 ? 16 : 0) : "memory");
}
#define CP_COMMIT() asm volatile("cp.async.commit_group;" ::: "memory")
#define CP_WAIT(n)  asm volatile("cp.async.wait_group %0;" :: "n"(n) : "memory")

__device__ __forceinline__ void ldsm_x4(uint32_t* r, uint32_t addr) {
    asm volatile("ldmatrix.sync.aligned.m8n8.x4.shared.b16 {%0,%1,%2,%3}, [%4];"
        : "=r"(r[0]), "=r"(r[1]), "=r"(r[2]), "=r"(r[3]) : "r"(addr));
}
__device__ __forceinline__ void ldsm_x2(uint32_t* r, uint32_t addr) {
    asm volatile("ldmatrix.sync.aligned.m8n8.x2.shared.b16 {%0,%1}, [%2];"
        : "=r"(r[0]), "=r"(r[1]) : "r"(addr));
}
__device__ __forceinline__ void mma16816(float* c, const uint32_t* a, const uint32_t* b) {
    asm volatile("mma.sync.aligned.m16n8k16.row.col.f32.bf16.bf16.f32 "
        "{%0,%1,%2,%3}, {%4,%5,%6,%7}, {%8,%9}, {%0,%1,%2,%3};"
        : "+f"(c[0]), "+f"(c[1]), "+f"(c[2]), "+f"(c[3])
        : "r"(a[0]), "r"(a[1]), "r"(a[2]), "r"(a[3]), "r"(b[0]), "r"(b[1]));
}
__device__ __forceinline__ void split4(float4 v, ull& hb, ull& lb) {
    __nv_bfloat16 h0 = __float2bfloat16(v.x), h1 = __float2bfloat16(v.y);
    __nv_bfloat16 h2 = __float2bfloat16(v.z), h3 = __float2bfloat16(v.w);
    __nv_bfloat16 l0 = __float2bfloat16(v.x - __bfloat162float(h0));
    __nv_bfloat16 l1 = __float2bfloat16(v.y - __bfloat162float(h1));
    __nv_bfloat16 l2 = __float2bfloat16(v.z - __bfloat162float(h2));
    __nv_bfloat16 l3 = __float2bfloat16(v.w - __bfloat162float(h3));
    hb = (ull)__bfloat16_as_ushort(h0) | ((ull)__bfloat16_as_ushort(h1) << 16) |
         ((ull)__bfloat16_as_ushort(h2) << 32) | ((ull)__bfloat16_as_ushort(h3) << 48);
    lb = (ull)__bfloat16_as_ushort(l0) | ((ull)__bfloat16_as_ushort(l1) << 16) |
         ((ull)__bfloat16_as_ushort(l2) << 32) | ((ull)__bfloat16_as_ushort(l3) << 48);
}

// ---------------------------------------------------------------------------
__global__ void zero_kernel() {
    int idx = blockIdx.x * blockDim.x + threadIdx.x;
    if (idx < NNODES) g_cnt[idx] = 0;
    if (idx < CH) { g_sum[idx] = 0.f; g_sumsq[idx] = 0.f; }
}

// split ea [E x 64] -> hi/lo
__global__ void __launch_bounds__(256) ea_split(const float* __restrict__ ea, int E) {
    int idx = blockIdx.x * blockDim.x + threadIdx.x;
    int stride = gridDim.x * blockDim.x;
    int total = E * ECH / 4;
    for (int i = idx; i < total; i += stride) {
        float4 v = __ldg(((const float4*)ea) + i);
        ull hb, lb; split4(v, hb, lb);
        ((ull*)g_ea_hi)[i] = hb;
        ((ull*)g_ea_lo)[i] = lb;
    }
}
// split x [N x 256] -> hi/lo
__global__ void __launch_bounds__(256) x_split(const float* __restrict__ x) {
    int idx = blockIdx.x * blockDim.x + threadIdx.x;
    int stride = gridDim.x * blockDim.x;
    const int total = NNODES * CH / 4;
    for (int i = idx; i < total; i += stride) {
        float4 v = __ldg(((const float4*)x) + i);
        ull hb, lb; split4(v, hb, lb);
        ((ull*)g_x_hi)[i] = hb;
        ((ull*)g_x_lo)[i] = lb;
    }
}

// weight transpose + split. grid 256 (n), block 256 (k)
__global__ void __launch_bounds__(256) wprep_kernel(
    const float* __restrict__ We, const float* __restrict__ Wrel,
    const float* __restrict__ Wroot, const float* __restrict__ Wres)
{
    int n = blockIdx.x;
    int k = threadIdx.x;
    if (k < ECH) {
        float v = __ldg(&We[(size_t)k * CH + n]);
        __nv_bfloat16 h = __float2bfloat16(v);
        g_WTe_hi[n * ECH + k] = h;
        g_WTe_lo[n * ECH + k] = __float2bfloat16(v - __bfloat162float(h));
    }
    {
        float v = __ldg(&Wrel[(size_t)k * CH + n]);
        __nv_bfloat16 h = __float2bfloat16(v);
        g_WTrel_hi[n * CH + k] = h;
        g_WTrel_lo[n * CH + k] = __float2bfloat16(v - __bfloat162float(h));
    }
    {
        float v = __ldg(&Wroot[(size_t)k * CH + n]);
        __nv_bfloat16 h = __float2bfloat16(v);
        g_WTroot_hi[n * CH + k] = h;
        g_WTroot_lo[n * CH + k] = __float2bfloat16(v - __bfloat162float(h));
    }
    {
        float v = __ldg(&Wres[(size_t)k * CH + n]);
        __nv_bfloat16 h = __float2bfloat16(v);
        g_WTres_hi[n * CH + k] = h;
        g_WTres_lo[n * CH + k] = __float2bfloat16(v - __bfloat162float(h));
    }
}

// ---------------------------------------------------------------------------
// CSR build
// ---------------------------------------------------------------------------
__global__ void hist_kernel(const int* __restrict__ ei, int E) {
    int e = blockIdx.x * blockDim.x + threadIdx.x;
    if (e < E) atomicAdd(&g_cnt[__ldg(&ei[E + e])], 1);
}
__global__ void __launch_bounds__(1024) scan_kernel(int E) {
    __shared__ int sp[1024];
    const int t = threadIdx.x;
    const int CHUNK = (NNODES + 1023) / 1024;  // 20
    int beg = t * CHUNK;
    int end = min(beg + CHUNK, NNODES);
    int mysum = 0;
    for (int i = beg; i < end; i++) mysum += g_cnt[i];
    sp[t] = mysum;
    __syncthreads();
#pragma unroll
    for (int off = 1; off < 1024; off <<= 1) {
        int v = (t >= off) ? sp[t - off] : 0;
        __syncthreads();
        sp[t] += v;
        __syncthreads();
    }
    int running = sp[t] - mysum;
    for (int i = beg; i < end; i++) {
        int c = g_cnt[i];
        g_rowstart[i] = running;
        g_cursor[i] = running;
        running += c;
    }
    if (t == 1023) g_rowstart[NNODES] = E;
}
__global__ void fill_kernel(const int* __restrict__ ei, int E) {
    int e = blockIdx.x * blockDim.x + threadIdx.x;
    if (e < E) {
        int dst = __ldg(&ei[E + e]);
        int src = __ldg(&ei[e]);
        int pos = atomicAdd(&g_cursor[dst], 1);
        g_csr[pos] = make_int2(e, src);
    }
}

// ---------------------------------------------------------------------------
// egemm: g_e = ea @ We^T.  Tile 128m x 128n, K=64 single chunk.
// 256 thr = 8 warps (2m x 4n), warp 64x32. smem 64KB -> multi-CTA/SM overlap.
// ---------------------------------------------------------------------------
__global__ void __launch_bounds__(256) egemm_mma(int E) {
    extern __shared__ char dsm[];
    char* base = (char*)(((uintptr_t)dsm + 1023) & ~(uintptr_t)1023);
    char* Ah = base;
    char* Al = base + 16384;
    char* Bh = base + 32768;
    char* Bl = base + 49152;

    const int tid = threadIdx.x;
    const int lane = tid & 31;
    const int wid = tid >> 5;
    const int wm = wid >> 2;     // 0..1
    const int wn = wid & 3;      // 0..3
    const int m0 = blockIdx.x * 128;
    const int n0 = blockIdx.y * 128;

    // A: 128 rows x 64k bf16 (128B/row) x2 buffers; 8 chunks16/row
    for (int idx = tid; idx < 1024; idx += 256) {
        int row = idx >> 3, q = idx & 7;
        int e = m0 + row;
        int ok = (e < E);
        int er = ok ? e : 0;
        uint32_t off = SWZ(row * 128 + q * 16);
        cpa16(smem_u32(Ah) + off, (const char*)g_ea_hi + (size_t)er * 128 + q * 16, ok);
        cpa16(smem_u32(Al) + off, (const char*)g_ea_lo + (size_t)er * 128 + q * 16, ok);
    }
    // B: 128 n-rows x 64k
    for (int idx = tid; idx < 1024; idx += 256) {
        int n = idx >> 3, q = idx & 7;
        uint32_t off = SWZ(n * 128 + q * 16);
        cpa16(smem_u32(Bh) + off, (const char*)g_WTe_hi + (size_t)(n0 + n) * 128 + q * 16, 1);
        cpa16(smem_u32(Bl) + off, (const char*)g_WTe_lo + (size_t)(n0 + n) * 128 + q * 16, 1);
    }
    CP_COMMIT();
    CP_WAIT(0);
    __syncthreads();

    float acc[4][4][4];
#pragma unroll
    for (int i = 0; i < 4; i++)
#pragma unroll
        for (int j = 0; j < 4; j++)
#pragma unroll
            for (int k = 0; k < 4; k++) acc[i][j][k] = 0.f;

    const uint32_t ah = smem_u32(Ah), al = smem_u32(Al);
    const uint32_t bh = smem_u32(Bh), bl = smem_u32(Bl);
    const uint32_t abase[3] = {ah, ah, al};
    const uint32_t bbase[3] = {bh, bl, bh};

#pragma unroll
    for (int p = 0; p < 3; p++) {
#pragma unroll
        for (int ks = 0; ks < 4; ks++) {
            int ko = ks * 32;
            uint32_t af[4][4], bf[4][2];
#pragma unroll
            for (int i = 0; i < 4; i++)
                ldsm_x4(af[i], abase[p] +
                    SWZ((wm * 64 + i * 16 + (lane & 15)) * 128 + ko + (lane >> 4) * 16));
#pragma unroll
            for (int j = 0; j < 4; j++)
                ldsm_x2(bf[j], bbase[p] +
                    SWZ((wn * 32 + j * 8 + (lane & 7)) * 128 + ko + ((lane >> 3) & 1) * 16));
#pragma unroll
            for (int i = 0; i < 4; i++)
#pragma unroll
                for (int j = 0; j < 4; j++) mma16816(acc[i][j], af[i], bf[j]);
        }
    }

    const int g = lane >> 2, tig = lane & 3;
#pragma unroll
    for (int i = 0; i < 4; i++) {
        int r0 = m0 + wm * 64 + i * 16 + g;
#pragma unroll
        for (int j = 0; j < 4; j++) {
            int c = n0 + wn * 32 + j * 8 + 2 * tig;
            if (r0 < E)
                *(float2*)(g_e + (size_t)r0 * CH + c) = make_float2(acc[i][j][0], acc[i][j][1]);
            if (r0 + 8 < E)
                *(float2*)(g_e + (size_t)(r0 + 8) * CH + c) = make_float2(acc[i][j][2], acc[i][j][3]);
        }
    }
}

// ---------------------------------------------------------------------------
// agg: agg[n] = sum_e g_e[e] * x[src]; writes bf16 hi/lo split directly.
// ---------------------------------------------------------------------------
__global__ void __launch_bounds__(256) agg_kernel(const float* __restrict__ x) {
    const int c = threadIdx.x;
    for (int n = blockIdx.x; n < NNODES; n += gridDim.x) {
        int beg = g_rowstart[n];
        int end = g_rowstart[n + 1];
        float a0 = 0.f, a1 = 0.f, a2 = 0.f, a3 = 0.f;
        int i = beg;
        for (; i + 4 <= end; i += 4) {
            int2 e0 = __ldg(&g_csr[i + 0]);
            int2 e1 = __ldg(&g_csr[i + 1]);
            int2 e2 = __ldg(&g_csr[i + 2]);
            int2 e3 = __ldg(&g_csr[i + 3]);
            a0 = fmaf(__ldg(&g_e[(size_t)e0.x * CH + c]), __ldg(&x[(size_t)e0.y * CH + c]), a0);
            a1 = fmaf(__ldg(&g_e[(size_t)e1.x * CH + c]), __ldg(&x[(size_t)e1.y * CH + c]), a1);
            a2 = fmaf(__ldg(&g_e[(size_t)e2.x * CH + c]), __ldg(&x[(size_t)e2.y * CH + c]), a2);
            a3 = fmaf(__ldg(&g_e[(size_t)e3.x * CH + c]), __ldg(&x[(size_t)e3.y * CH + c]), a3);
        }
        for (; i < end; i++) {
            int2 e0 = __ldg(&g_csr[i]);
            a0 = fmaf(__ldg(&g_e[(size_t)e0.x * CH + c]),
                      __ldg(&x[(size_t)e0.y * CH + c]), a0);
        }
        float v = (a0 + a1) + (a2 + a3);
        __nv_bfloat16 h = __float2bfloat16(v);
        g_agg_hi[(size_t)n * CH + c] = h;
        g_agg_lo[(size_t)n * CH + c] = __float2bfloat16(v - __bfloat162float(h));
    }
}

// ---------------------------------------------------------------------------
// node MMA, double-buffered cp.async pipeline.
// grid (157, 4): yb 0/1 -> h cols [yb*128, +128) (A=agg then A=x, W_rel/W_root)
//                yb 2/3 -> res cols (A=x, W_res) -> out
// tile 128m x 128n; K=256 in 4 chunks of 64.
// smem: 2 x (Ah 16K | Al 16K | Bh 16K | Bl 16K) = 128KB
// ---------------------------------------------------------------------------
__global__ void __launch_bounds__(256) node_mma(
    const float* __restrict__ b_rel, float* __restrict__ out)
{
    extern __shared__ char dsm[];
    char* base = (char*)(((uintptr_t)dsm + 1023) & ~(uintptr_t)1023);

    const int tid = threadIdx.x;
    const int lane = tid & 31;
    const int wid = tid >> 5;
    const int wm = wid >> 2;
    const int wn = wid & 3;
    const int m0 = blockIdx.x * 128;
    const int yb = blockIdx.y;
    const bool isH = (yb < 2);
    const int n0 = (isH ? yb : yb - 2) * 128;

    const __nv_bfloat16* Asrc_hi[2];
    const __nv_bfloat16* Asrc_lo[2];
    const __nv_bfloat16* Bsrc_hi[2];
    const __nv_bfloat16* Bsrc_lo[2];
    int nsrc;
    if (isH) {
        nsrc = 2;
        Asrc_hi[0] = g_agg_hi; Asrc_lo[0] = g_agg_lo;
        Bsrc_hi[0] = g_WTrel_hi; Bsrc_lo[0] = g_WTrel_lo;
        Asrc_hi[1] = g_x_hi; Asrc_lo[1] = g_x_lo;
        Bsrc_hi[1] = g_WTroot_hi; Bsrc_lo[1] = g_WTroot_lo;
    } else {
        nsrc = 1;
        Asrc_hi[0] = g_x_hi; Asrc_lo[0] = g_x_lo;
        Bsrc_hi[0] = g_WTres_hi; Bsrc_lo[0] = g_WTres_lo;
    }
    const int np = nsrc * 4;

    // prefetch phase p into buffer b
    auto prefetch = [&](int p, int b) {
        int s = p >> 2, kc = p & 3;
        int k0b = kc * 128;  // byte offset into 512B row
        char* Ah = base + b * 65536;
        char* Al = Ah + 16384;
        char* Bh = Ah + 32768;
        char* Bl = Ah + 49152;
        const char* ah = (const char*)Asrc_hi[s];
        const char* al = (const char*)Asrc_lo[s];
        const char* bh = (const char*)Bsrc_hi[s];
        const char* bl = (const char*)Bsrc_lo[s];
        for (int idx = tid; idx < 1024; idx += 256) {
            int row = idx >> 3, q = idx & 7;
            int r = m0 + row;
            int ok = (r < NNODES);
            int rr = ok ? r : 0;
            uint32_t off = SWZ(row * 128 + q * 16);
            cpa16(smem_u32(Ah) + off, ah + (size_t)rr * 512 + k0b + q * 16, ok);
            cpa16(smem_u32(Al) + off, al + (size_t)rr * 512 + k0b + q * 16, ok);
        }
        for (int idx = tid; idx < 1024; idx += 256) {
            int n = idx >> 3, q = idx & 7;
            uint32_t off = SWZ(n * 128 + q * 16);
            cpa16(smem_u32(Bh) + off, bh + (size_t)(n0 + n) * 512 + k0b + q * 16, 1);
            cpa16(smem_u32(Bl) + off, bl + (size_t)(n0 + n) * 512 + k0b + q * 16, 1);
        }
        CP_COMMIT();
    };

    float acc[4][4][4];
#pragma unroll
    for (int i = 0; i < 4; i++)
#pragma unroll
        for (int j = 0; j < 4; j++)
#pragma unroll
            for (int k = 0; k < 4; k++) acc[i][j][k] = 0.f;

    prefetch(0, 0);
    for (int p = 0; p < np; p++) {
        if (p + 1 < np) {
            prefetch(p + 1, (p + 1) & 1);
            CP_WAIT(1);
        } else {
            CP_WAIT(0);
        }
        __syncthreads();
        char* Ab = base + (p & 1) * 65536;
        const uint32_t ah = smem_u32(Ab), al = ah + 16384;
        const uint32_t bh = ah + 32768, bl = ah + 49152;
        const uint32_t abase[3] = {ah, ah, al};
        const uint32_t bbase[3] = {bh, bl, bh};
#pragma unroll
        for (int pp = 0; pp < 3; pp++) {
#pragma unroll
            for (int ks = 0; ks < 4; ks++) {
                int ko = ks * 32;
                uint32_t af[4][4], bf[4][2];
#pragma unroll
                for (int i = 0; i < 4; i++)
                    ldsm_x4(af[i], abase[pp] +
                        SWZ((wm * 64 + i * 16 + (lane & 15)) * 128 + ko + (lane >> 4) * 16));
#pragma unroll
                for (int j = 0; j < 4; j++)
                    ldsm_x2(bf[j], bbase[pp] +
                        SWZ((wn * 32 + j * 8 + (lane & 7)) * 128 + ko + ((lane >> 3) & 1) * 16));
#pragma unroll
                for (int i = 0; i < 4; i++)
#pragma unroll
                    for (int j = 0; j < 4; j++) mma16816(acc[i][j], af[i], bf[j]);
            }
        }
        __syncthreads();
    }

    // epilogue
    const int g = lane >> 2, tig = lane & 3;
    if (isH) {
        float cs[4][2], cq[4][2];
#pragma unroll
        for (int j = 0; j < 4; j++) { cs[j][0] = cs[j][1] = cq[j][0] = cq[j][1] = 0.f; }
#pragma unroll
        for (int j = 0; j < 4; j++) {
            int c = n0 + wn * 32 + j * 8 + 2 * tig;
            float2 b = *(const float2*)(b_rel + c);
#pragma unroll
            for (int i = 0; i < 4; i++) {
                int r0 = m0 + wm * 64 + i * 16 + g;
                if (r0 < NNODES) {
                    float v0 = fmaxf(acc[i][j][0] + b.x, 0.f);
                    float v1 = fmaxf(acc[i][j][1] + b.y, 0.f);
                    *(float2*)(g_h + (size_t)r0 * CH + c) = make_float2(v0, v1);
                    cs[j][0] += v0; cs[j][1] += v1;
                    cq[j][0] += v0 * v0; cq[j][1] += v1 * v1;
                }
                if (r0 + 8 < NNODES) {
                    float v0 = fmaxf(acc[i][j][2] + b.x, 0.f);
                    float v1 = fmaxf(acc[i][j][3] + b.y, 0.f);
                    *(float2*)(g_h + (size_t)(r0 + 8) * CH + c) = make_float2(v0, v1);
                    cs[j][0] += v0; cs[j][1] += v1;
                    cq[j][0] += v0 * v0; cq[j][1] += v1 * v1;
                }
            }
        }
        // reduce over g (lanes stride 4, same tig)
#pragma unroll
        for (int j = 0; j < 4; j++)
#pragma unroll
            for (int t2 = 0; t2 < 2; t2++) {
#pragma unroll
                for (int m = 4; m <= 16; m <<= 1) {
                    cs[j][t2] += __shfl_xor_sync(0xFFFFFFFF, cs[j][t2], m);
                    cq[j][t2] += __shfl_xor_sync(0xFFFFFFFF, cq[j][t2], m);
                }
            }
        if (lane < 4) {
#pragma unroll
            for (int j = 0; j < 4; j++) {
                int c = n0 + wn * 32 + j * 8 + 2 * lane;
                atomicAdd(&g_sum[c], cs[j][0]);
                atomicAdd(&g_sum[c + 1], cs[j][1]);
                atomicAdd(&g_sumsq[c], cq[j][0]);
                atomicAdd(&g_sumsq[c + 1], cq[j][1]);
            }
        }
    } else {
#pragma unroll
        for (int j = 0; j < 4; j++) {
            int c = n0 + wn * 32 + j * 8 + 2 * tig;
#pragma unroll
            for (int i = 0; i < 4; i++) {
                int r0 = m0 + wm * 64 + i * 16 + g;
                if (r0 < NNODES)
                    *(float2*)(out + (size_t)r0 * CH + c) = make_float2(acc[i][j][0], acc[i][j][1]);
                if (r0 + 8 < NNODES)
                    *(float2*)(out + (size_t)(r0 + 8) * CH + c) = make_float2(acc[i][j][2], acc[i][j][3]);
            }
        }
    }
}

// ---------------------------------------------------------------------------
// finalize: out = h*scale + shift + res  (res already in out)
// ---------------------------------------------------------------------------
__global__ void __launch_bounds__(256) finalize(
    const float* __restrict__ gamma, const float* __restrict__ beta,
    float* __restrict__ out)
{
    __shared__ float ssc[CH], ssh[CH];
    int t = threadIdx.x;
    {
        float m = g_sum[t] * (1.0f / NNODES);
        float var = g_sumsq[t] * (1.0f / NNODES) - m * m;
        float is = rsqrtf(var + 1e-5f);
        float sc = is * __ldg(&gamma[t]);
        ssc[t] = sc;
        ssh[t] = __ldg(&beta[t]) - m * sc;
    }
    __syncthreads();
    int idx = blockIdx.x * blockDim.x + t;
    int stride = gridDim.x * blockDim.x;
    const int total = NNODES * CH / 4;
    const float4* h4 = (const float4*)g_h;
    float4* o4 = (float4*)out;
    for (int i = idx; i < total; i += stride) {
        int c = (i & 63) * 4;
        float4 h = h4[i];
        float4 o = o4[i];
        float4 sc = *(const float4*)&ssc[c];
        float4 sh = *(const float4*)&ssh[c];
        o4[i] = make_float4(fmaf(h.x, sc.x, sh.x) + o.x,
                            fmaf(h.y, sc.y, sh.y) + o.y,
                            fmaf(h.z, sc.z, sh.z) + o.z,
                            fmaf(h.w, sc.w, sh.w) + o.w);
    }
}

// ---------------------------------------------------------------------------
extern "C" void kernel_launch(void* const* d_in, const int* in_sizes, int n_in,
                              void* d_out, int out_size) {
    const float* x      = (const float*)d_in[0];
    const int*   ei     = (const int*)d_in[1];
    const float* ea     = (const float*)d_in[2];
    const float* W_edge = (const float*)d_in[3];
    const float* W_rel  = (const float*)d_in[4];
    const float* b_rel  = (const float*)d_in[5];
    const float* W_root = (const float*)d_in[6];
    const float* gamma  = (const float*)d_in[7];
    const float* beta   = (const float*)d_in[8];
    const float* W_res  = (const float*)d_in[9];
    int E = in_sizes[1] / 2;
    float* out = (float*)d_out;

    const int EGEMM_SMEM = 65536 + 1024;
    const int NODE_SMEM = 131072 + 1024;
    cudaFuncSetAttribute(egemm_mma, cudaFuncAttributeMaxDynamicSharedMemorySize, EGEMM_SMEM);
    cudaFuncSetAttribute(node_mma, cudaFuncAttributeMaxDynamicSharedMemorySize, NODE_SMEM);

    zero_kernel<<<(NNODES + 255) / 256, 256>>>();
    wprep_kernel<<<256, 256>>>(W_edge, W_rel, W_root, W_res);
    ea_split<<<1184, 256>>>(ea, E);
    x_split<<<1184, 256>>>(x);
    hist_kernel<<<(E + 255) / 256, 256>>>(ei, E);
    scan_kernel<<<1, 1024>>>(E);
    fill_kernel<<<(E + 255) / 256, 256>>>(ei, E);
    dim3 ge((E + 127) / 128, 2);
    egemm_mma<<<ge, 256, EGEMM_SMEM>>>(E);
    agg_kernel<<<592, 256>>>(x);
    dim3 gn((NNODES + 127) / 128, 4);
    node_mma<<<gn, 256, NODE_SMEM>>>(b_rel, out);
    finalize<<<592, 256>>>(gamma, beta, out);
}